// round 13
// baseline (speedup 1.0000x reference)
#include <cuda_runtime.h>
#include <cuda_bf16.h>
#include <cstdint>
#include <math.h>

#define D_MODEL 64
#define HID     128
#define NRULES  4
#define K1      192
#define TT      8192
#define NTOK    (32*TT)
#define NBLK    (NTOK/128)
#define NTHR    512
#define LN_EPS  1e-5f

#define CP2P 36                    // cells pitch (uint2), conflict-free LDS.64
#define W1P4 130                   // W1 pitch (uint4), ≡2 mod 8 -> conflict-free LDS.128
#define W2P4 66                    // W2 pitch (uint4), ≡2 mod 8

#define SEG_BYTES (16*W1P4*16)     // 33280
#define SEG_U4    (SEG_BYTES/16)   // 2080
#define W2_BYTES  (32*W2P4*16)     // 33792
#define W2_U4     (W2_BYTES/16)    // 2112

// smem layout (bytes)
#define OFF_W0B  37440
#define OFF_W1B  (OFF_W0B + SEG_BYTES)     // 70720
#define OFF_W2B  (OFF_W1B + SEG_BYTES)     // 104000
#define OFF_XCHB (OFF_W2B + W2_BYTES)      // 137792
#define SMEM_BYTES (OFF_XCHB + 32768)      // 170560

__device__ float g_rw[4];
__device__ float g_alpha;
__device__ int   g_nev;
__device__ float g_buf0[(size_t)NTOK*D_MODEL];
__device__ float g_buf1[(size_t)NTOK*D_MODEL];
__device__ __align__(16) uint4 g_w1p4[NRULES*3*SEG_U4];
__device__ __align__(16) uint4 g_w2p4[NRULES*W2_U4];

__device__ __forceinline__ float gelu_exact(float x){
    return 0.5f * x * (1.0f + erff(x * 0.7071067811865475f));
}
// A&S 7.1.26 erf (abs err <= 1.5e-7)
__device__ __forceinline__ float gelu_fast(float x){
    float z  = 0.70710678118f * x;
    float az = fabsf(z);
    float t  = __fdividef(1.0f, fmaf(0.3275911f, az, 1.0f));
    float p  = t*fmaf(t, fmaf(t, fmaf(t, fmaf(t, 1.061405429f, -1.453152027f),
                1.421413741f), -0.284496736f), 0.254829592f);
    float e  = __expf(-z*z);
    float er = copysignf(fmaf(-p, e, 1.0f), z);
    return 0.5f * x * (1.0f + er);
}
__device__ __forceinline__ float tanh_fast(float x){
    float e = __expf(2.0f*x);
    return 1.0f - __fdividef(2.0f, e + 1.0f);
}
__device__ __forceinline__ void pack_hilo(float2 v, uint32_t& hi, uint32_t& lo){
    __nv_bfloat162 hb = __float22bfloat162_rn(v);
    float2 lv;
    lv.x = v.x - __bfloat162float(hb.x);
    lv.y = v.y - __bfloat162float(hb.y);
    __nv_bfloat162 lb = __float22bfloat162_rn(lv);
    hi = *(uint32_t*)&hb;
    lo = *(uint32_t*)&lb;
}
__device__ __forceinline__ void mma_bf16(float* d,
    uint32_t a0, uint32_t a1, uint32_t a2, uint32_t a3,
    uint32_t b0, uint32_t b1)
{
    asm volatile(
        "mma.sync.aligned.m16n8k16.row.col.f32.bf16.bf16.f32 "
        "{%0,%1,%2,%3},{%4,%5,%6,%7},{%8,%9},{%0,%1,%2,%3};"
        : "+f"(d[0]), "+f"(d[1]), "+f"(d[2]), "+f"(d[3])
        : "r"(a0), "r"(a1), "r"(a2), "r"(a3), "r"(b0), "r"(b1));
}

__device__ __forceinline__ void cp_copy16(void* dst, const void* src, int n16, int tid){
    uint32_t sbase = (uint32_t)__cvta_generic_to_shared(dst);
    const uint4* s = (const uint4*)src;
    for (int i = tid; i < n16; i += NTHR)
        asm volatile("cp.async.cg.shared.global [%0], [%1], 16;"
                     :: "r"(sbase + i*16), "l"(s + i));
}
#define CP_COMMIT() asm volatile("cp.async.commit_group;" ::: "memory")
#define CP_WAIT0()  asm volatile("cp.async.wait_group 0;" ::: "memory")

// ---------------- one-shot weight packing (uint4 fragment layout) ----------
__global__ void pack_weights(const float* __restrict__ rw1,
                             const float* __restrict__ rw2)
{
    int i = blockIdx.x * blockDim.x + threadIdx.x;
    if (i < NRULES*3*16*128){
        int n    = i & 127;
        int rowq = (i >> 7) & 15;
        int rs   = i >> 11;
        int kt = rowq >> 2, tig = rowq & 3;
        int kp = kt*8 + tig;
        const float* w = rw1 + ((size_t)(rs/3)*K1 + (rs%3)*64) * HID;
        float2 v0, v1;
        v0.x = w[(size_t)(2*kp)   * HID + n];
        v0.y = w[(size_t)(2*kp+1) * HID + n];
        v1.x = w[(size_t)(2*kp+8) * HID + n];
        v1.y = w[(size_t)(2*kp+9) * HID + n];
        uint32_t h0,l0,h1,l1;
        pack_hilo(v0, h0, l0);
        pack_hilo(v1, h1, l1);
        g_w1p4[(size_t)rs*SEG_U4 + rowq*W1P4 + n] = make_uint4(h0,l0,h1,l1);
    } else {
        int q = i - NRULES*3*16*128;
        if (q >= NRULES*32*64) return;
        int n    = q & 63;
        int rowq = (q >> 6) & 31;
        int r    = q >> 11;
        int ktg = rowq >> 2, tig = rowq & 3;
        int kp = ktg*8 + tig;
        const float* w = rw2 + (size_t)r * HID * D_MODEL;
        float2 v0, v1;
        v0.x = w[(size_t)(2*kp)   * D_MODEL + n];
        v0.y = w[(size_t)(2*kp+1) * D_MODEL + n];
        v1.x = w[(size_t)(2*kp+8) * D_MODEL + n];
        v1.y = w[(size_t)(2*kp+9) * D_MODEL + n];
        uint32_t h0,l0,h1,l1;
        pack_hilo(v0, h0, l0);
        pack_hilo(v1, h1, l1);
        g_w2p4[(size_t)r*W2_U4 + rowq*W2P4 + n] = make_uint4(h0,l0,h1,l1);
    }
}

// ---------------- control kernel ----------------
__global__ void control_kernel(
    const float* __restrict__ c,
    const float* __restrict__ sw1, const float* __restrict__ sb1,
    const float* __restrict__ sw2, const float* __restrict__ sb2,
    const float* __restrict__ tw1, const float* __restrict__ tb1,
    const float* __restrict__ tw2, const float* __restrict__ tb2,
    const float* __restrict__ qw1, const float* __restrict__ qb1,
    const float* __restrict__ qw2, const float* __restrict__ qb2)
{
    __shared__ float cs[128], h1[64], h2[32], h3[32];
    int t = threadIdx.x;
    if (t < 128) cs[t] = c[t];
    __syncthreads();
    if (t < 64){
        float a = sb1[t];
        for (int k = 0; k < 128; k++) a += cs[k] * sw1[k*64 + t];
        h1[t] = gelu_exact(a);
    } else if (t < 96){
        int i = t - 64; float a = tb1[i];
        for (int k = 0; k < 128; k++) a += cs[k] * tw1[k*32 + i];
        h2[i] = gelu_exact(a);
    } else {
        int i = t - 96; float a = qb1[i];
        for (int k = 0; k < 128; k++) a += cs[k] * qw1[k*32 + i];
        h3[i] = gelu_exact(a);
    }
    __syncthreads();
    if (t == 0){
        float l[4], mx = -1e30f;
        for (int r = 0; r < 4; r++){
            float a = sb2[r];
            for (int i = 0; i < 64; i++) a += h1[i] * sw2[i*4 + r];
            l[r] = a; mx = fmaxf(mx, a);
        }
        float s = 0.f;
        for (int r = 0; r < 4; r++){ l[r] = expf(l[r]-mx); s += l[r]; }
        for (int r = 0; r < 4; r++) g_rw[r] = l[r]/s;
    }
    if (t == 1){
        float l[7], mx = -1e30f;
        for (int q = 0; q < 7; q++){
            float a = tb2[q];
            for (int i = 0; i < 32; i++) a += h2[i] * tw2[i*7 + q];
            l[q] = a; mx = fmaxf(mx, a);
        }
        float s = 0.f;
        for (int q = 0; q < 7; q++){ l[q] = expf(l[q]-mx); s += l[q]; }
        float nf = 0.f;
        for (int q = 0; q < 7; q++) nf += (l[q]/s) * (float)(q+2);
        int n = (int)(nf + 0.5f);
        g_nev = n < 2 ? 2 : (n > 8 ? 8 : n);
    }
    if (t == 2){
        float v = qb2[0];
        for (int i = 0; i < 32; i++) v += h3[i] * qw2[i];
        g_alpha = 0.1f + 0.8f / (1.0f + expf(-v));
    }
}

// one GEMM1 segment: 4 k-tiles x 8 n-tiles x 3 terms (B via LDS.128)
__device__ __forceinline__ void gemm1_seg(float acc[8][4], const uint4* wseg,
    const uint2* apr, const uint2* bpr, int half, int g, int tig)
{
    #pragma unroll
    for (int kt = 0; kt < 4; kt++){
        const int kp = kt*8 + tig;
        uint2 A0 = apr[kp],   A1 = bpr[kp];
        uint2 A2 = apr[kp+4], A3 = bpr[kp+4];
        const uint4* br = wseg + (size_t)(kt*4 + tig)*W1P4;
        #pragma unroll
        for (int ntl = 0; ntl < 8; ntl++){
            uint4 qv = br[(half*8 + ntl)*8 + g];
            mma_bf16(acc[ntl], A0.x,A1.x,A2.x,A3.x, qv.x, qv.z);
            mma_bf16(acc[ntl], A0.y,A1.y,A2.y,A3.y, qv.x, qv.z);
            mma_bf16(acc[ntl], A0.x,A1.x,A2.x,A3.x, qv.y, qv.w);
        }
    }
}

// ---------------- evolve step ----------------
__global__ void __launch_bounds__(NTHR, 1)
step_kernel(const float* __restrict__ cells_in,
            const float* __restrict__ rb1, const float* __restrict__ rb2,
            int j)
{
    if (j >= g_nev) return;

    extern __shared__ char smc[];
    uint2*  cp  = (uint2*)smc;
    uint4*  wb0 = (uint4*)(smc + OFF_W0B);
    uint4*  wb1 = (uint4*)(smc + OFF_W1B);
    uint4*  w2s = (uint4*)(smc + OFF_W2B);
    float4* xb  = (float4*)(smc + OFF_XCHB);
    uint4*  wb[2] = {wb0, wb1};

    const float* src = (j == 0) ? cells_in : ((j & 1) ? g_buf0 : g_buf1);
    float*       dst = (j & 1) ? g_buf1 : g_buf0;

    const int tid  = threadIdx.x;
    const int w    = tid >> 5;
    const int lane = tid & 31;
    const int g    = lane >> 2;
    const int tig  = lane & 3;
    const int half = w >> 3;
    const int wp   = w & 7;
    const int m0   = wp * 16;

    const int brow = blockIdx.x >> 6;
    const int t0   = (blockIdx.x & 63) << 7;
    const float* rowbase = src + (size_t)brow * TT * D_MODEL;

    // prefetch rule0 seg0 while building the cells tile
    cp_copy16(wb0, g_w1p4, SEG_U4, tid);
    CP_COMMIT();

    for (int i = tid; i < 130*32; i += NTHR){
        int row = i >> 5, kp = i & 31;
        int t = (t0 - 1 + row) & (TT - 1);
        float2 v = *(const float2*)(rowbase + (size_t)t * D_MODEL + 2*kp);
        uint32_t hi, lo;
        pack_hilo(v, hi, lo);
        cp[row*CP2P + kp] = make_uint2(hi, lo);
    }
    CP_WAIT0();
    __syncthreads();

    float outa[16];
    #pragma unroll
    for (int i = 0; i < 16; i++) outa[i] = 0.0f;

    for (int r = 0; r < NRULES; r++){
        const int b = r & 1;
        const uint2* apr0 = cp + (size_t)(m0 + 1 + g) * CP2P;   // cells[t]
        const uint2* apr1 = cp + (size_t)(m0 + 0 + g) * CP2P;   // cells[t-1]
        const uint2* apr2 = cp + (size_t)(m0 + 2 + g) * CP2P;   // cells[t+1]

        float acc[8][4];
        #pragma unroll
        for (int a = 0; a < 8; a++){
            acc[a][0]=0.f; acc[a][1]=0.f; acc[a][2]=0.f; acc[a][3]=0.f;
        }

        // [A] prefetch seg1 + W2(r); compute seg0
        cp_copy16(wb[b^1], g_w1p4 + (size_t)(r*3+1)*SEG_U4, SEG_U4, tid);
        cp_copy16(w2s,     g_w2p4 + (size_t)r*W2_U4,        W2_U4,  tid);
        CP_COMMIT();
        gemm1_seg(acc, wb[b], apr0, apr0 + 8*CP2P, half, g, tig);
        CP_WAIT0();
        __syncthreads();

        // [B] prefetch seg2; compute seg1
        cp_copy16(wb[b], g_w1p4 + (size_t)(r*3+2)*SEG_U4, SEG_U4, tid);
        CP_COMMIT();
        gemm1_seg(acc, wb[b^1], apr1, apr1 + 8*CP2P, half, g, tig);
        CP_WAIT0();
        __syncthreads();

        // [C] prefetch next rule seg0; compute seg2
        if (r < NRULES-1)
            cp_copy16(wb[b^1], g_w1p4 + (size_t)((r+1)*3)*SEG_U4, SEG_U4, tid);
        CP_COMMIT();
        gemm1_seg(acc, wb[b], apr2, apr2 + 8*CP2P, half, g, tig);

        // ===== FUSED epi1 + GEMM2: per k-chunk, convert 2 acc tiles ->
        // one 8-reg fragment, consume against all 8 n-tiles, let acc die.
        float acc2[8][4];
        #pragma unroll
        for (int a = 0; a < 8; a++){
            acc2[a][0]=0.f; acc2[a][1]=0.f; acc2[a][2]=0.f; acc2[a][3]=0.f;
        }
        #pragma unroll
        for (int ktl = 0; ktl < 4; ktl++){
            uint32_t fh[4], fl[4];
            #pragma unroll
            for (int sub = 0; sub < 2; sub++){
                int ntl = 2*ktl + sub;
                int c   = (half*8 + ntl)*8 + 2*tig;
                const float2 bb = __ldg((const float2*)(rb1 + r*HID + c));
                float2 va, vb;
                va.x = gelu_fast(acc[ntl][0] + bb.x);
                va.y = gelu_fast(acc[ntl][1] + bb.y);
                vb.x = gelu_fast(acc[ntl][2] + bb.x);
                vb.y = gelu_fast(acc[ntl][3] + bb.y);
                pack_hilo(va, fh[sub*2],   fl[sub*2]);
                pack_hilo(vb, fh[sub*2+1], fl[sub*2+1]);
            }
            const uint4* br = w2s + (size_t)((half*4+ktl)*4 + tig)*W2P4;
            #pragma unroll
            for (int nt = 0; nt < 8; nt++){
                uint4 qv = br[nt*8 + g];
                mma_bf16(acc2[nt], fh[0],fh[1],fh[2],fh[3], qv.x, qv.z);
                mma_bf16(acc2[nt], fl[0],fl[1],fl[2],fl[3], qv.x, qv.z);
                mma_bf16(acc2[nt], fh[0],fh[1],fh[2],fh[3], qv.y, qv.w);
            }
        }

        // exchange: store the 4 n-tiles the PARTNER finalizes
        {
            const int sbase = (wp*2 + half)*4;
            const int pnt   = (1 - half)*4;       // partner's tile range
            #pragma unroll
            for (int q = 0; q < 4; q++)
                xb[(sbase + q)*32 + lane] = make_float4(
                    acc2[pnt+q][0], acc2[pnt+q][1], acc2[pnt+q][2], acc2[pnt+q][3]);
        }
        CP_WAIT0();
        __syncthreads();   // xchg visible + next seg0 staged

        // finalize: own partial + partner partial -> tanh -> outa
        {
            const int pbase = (wp*2 + (1 - half))*4;
            const int ont   = half*4;
            const float rr = g_rw[r];
            #pragma unroll
            for (int q = 0; q < 4; q++){
                float4 pp = xb[(pbase + q)*32 + lane];
                int c = (ont + q)*8 + 2*tig;
                const float2 bb = __ldg((const float2*)(rb2 + r*D_MODEL + c));
                outa[q*4+0] += rr * tanh_fast(acc2[ont+q][0] + pp.x + bb.x);
                outa[q*4+1] += rr * tanh_fast(acc2[ont+q][1] + pp.y + bb.y);
                outa[q*4+2] += rr * tanh_fast(acc2[ont+q][2] + pp.z + bb.x);
                outa[q*4+3] += rr * tanh_fast(acc2[ont+q][3] + pp.w + bb.y);
            }
        }
    }

    // residual mix + store
    {
        const float al = g_alpha, om = 1.0f - al;
        const float* sra = src + ((size_t)brow*TT + t0 + m0 + g) * D_MODEL;
        const float* srb = src + ((size_t)brow*TT + t0 + m0 + g + 8) * D_MODEL;
        float* da = dst + ((size_t)brow*TT + t0 + m0 + g) * D_MODEL;
        float* db = dst + ((size_t)brow*TT + t0 + m0 + g + 8) * D_MODEL;
        #pragma unroll
        for (int q = 0; q < 4; q++){
            int c = (half*4 + q)*8 + 2*tig;
            float2 cva = __ldg((const float2*)(sra + c));
            float2 cvb = __ldg((const float2*)(srb + c));
            float2 oa, ob;
            oa.x = al*cva.x + om*outa[q*4+0];
            oa.y = al*cva.y + om*outa[q*4+1];
            ob.x = al*cvb.x + om*outa[q*4+2];
            ob.y = al*cvb.y + om*outa[q*4+3];
            *(float2*)(da + c) = oa;
            *(float2*)(db + c) = ob;
        }
    }
}

// ---------------- final LayerNorm ----------------
__global__ void __launch_bounds__(256)
ln_kernel(const float* __restrict__ g, const float* __restrict__ b,
          float* __restrict__ out)
{
    const float* src = ((g_nev - 1) & 1) ? g_buf1 : g_buf0;
    int tok  = blockIdx.x * 8 + (threadIdx.x >> 5);
    int lane = threadIdx.x & 31;
    float2 v = ((const float2*)(src + (size_t)tok * D_MODEL))[lane];
    float s = v.x + v.y;
    #pragma unroll
    for (int o = 16; o; o >>= 1) s += __shfl_xor_sync(0xffffffffu, s, o);
    float mu = s * (1.0f/64.0f);
    float dx = v.x - mu, dy = v.y - mu;
    float ss = dx*dx + dy*dy;
    #pragma unroll
    for (int o = 16; o; o >>= 1) ss += __shfl_xor_sync(0xffffffffu, ss, o);
    float rstd = rsqrtf(ss * (1.0f/64.0f) + LN_EPS);
    float2 gg = ((const float2*)g)[lane];
    float2 bb = ((const float2*)b)[lane];
    float2 ov;
    ov.x = dx * rstd * gg.x + bb.x;
    ov.y = dy * rstd * gg.y + bb.y;
    ((float2*)(out + (size_t)tok * D_MODEL))[lane] = ov;
}

// ---------------- launch ----------------
extern "C" void kernel_launch(void* const* d_in, const int* in_sizes, int n_in,
                              void* d_out, int out_size)
{
    const float* cells = (const float*)d_in[0];
    cudaFuncSetAttribute(step_kernel,
                         cudaFuncAttributeMaxDynamicSharedMemorySize, SMEM_BYTES);

    control_kernel<<<1, 128>>>((const float*)d_in[1],
        (const float*)d_in[6],  (const float*)d_in[7],
        (const float*)d_in[8],  (const float*)d_in[9],
        (const float*)d_in[10], (const float*)d_in[11],
        (const float*)d_in[12], (const float*)d_in[13],
        (const float*)d_in[14], (const float*)d_in[15],
        (const float*)d_in[16], (const float*)d_in[17]);

    pack_weights<<<(NRULES*3*16*128 + NRULES*32*64 + 255)/256, 256>>>(
        (const float*)d_in[2], (const float*)d_in[4]);

    for (int j = 0; j < 8; j++)
        step_kernel<<<NBLK, NTHR, SMEM_BYTES>>>(cells,
            (const float*)d_in[3], (const float*)d_in[5], j);

    ln_kernel<<<NTOK/8, 256>>>((const float*)d_in[18], (const float*)d_in[19],
                               (float*)d_out);
}

// round 14
// speedup vs baseline: 1.1032x; 1.1032x over previous
#include <cuda_runtime.h>
#include <cuda_bf16.h>
#include <cstdint>
#include <math.h>

#define D_MODEL 64
#define HID     128
#define NRULES  4
#define K1      192
#define TT      8192
#define NTOK    (32*TT)
#define NBLK    (NTOK/64)          // 4096 CTAs, 64 tokens each
#define NTHR    256
#define LN_EPS  1e-5f

#define CP2P 36                    // cells pitch (uint2), conflict-free LDS.64
#define W1P4 130                   // W1 pitch (uint4), ≡2 mod 8 -> conflict-free LDS.128
#define W2P4 66                    // W2 pitch (uint4), ≡2 mod 8

#define SEG_BYTES (16*W1P4*16)     // 33280
#define SEG_U4    (SEG_BYTES/16)   // 2080
#define W2_BYTES  (32*W2P4*16)     // 33792
#define W2_U4     (W2_BYTES/16)    // 2112

// smem layout (bytes): cells 66*36*8 = 19008 | R0 33792 | R1 33792 | xchg 16384
#define OFF_R0B  19008
#define OFF_R1B  (OFF_R0B + 33792)         // 52800
#define OFF_XCHB (OFF_R1B + 33792)         // 86592
#define SMEM_BYTES (OFF_XCHB + 16384)      // 102976  (x2 CTAs = 205952 < 227KB)

__device__ float g_rw[4];
__device__ float g_alpha;
__device__ int   g_nev;
__device__ float g_buf0[(size_t)NTOK*D_MODEL];
__device__ float g_buf1[(size_t)NTOK*D_MODEL];
__device__ __align__(16) uint4 g_w1p4[NRULES*3*SEG_U4];
__device__ __align__(16) uint4 g_w2p4[NRULES*W2_U4];

__device__ __forceinline__ float gelu_exact(float x){
    return 0.5f * x * (1.0f + erff(x * 0.7071067811865475f));
}
// A&S 7.1.26 erf (abs err <= 1.5e-7)
__device__ __forceinline__ float gelu_fast(float x){
    float z  = 0.70710678118f * x;
    float az = fabsf(z);
    float t  = __fdividef(1.0f, fmaf(0.3275911f, az, 1.0f));
    float p  = t*fmaf(t, fmaf(t, fmaf(t, fmaf(t, 1.061405429f, -1.453152027f),
                1.421413741f), -0.284496736f), 0.254829592f);
    float e  = __expf(-z*z);
    float er = copysignf(fmaf(-p, e, 1.0f), z);
    return 0.5f * x * (1.0f + er);
}
__device__ __forceinline__ float tanh_fast(float x){
    float e = __expf(2.0f*x);
    return 1.0f - __fdividef(2.0f, e + 1.0f);
}
__device__ __forceinline__ void pack_hilo(float2 v, uint32_t& hi, uint32_t& lo){
    __nv_bfloat162 hb = __float22bfloat162_rn(v);
    float2 lv;
    lv.x = v.x - __bfloat162float(hb.x);
    lv.y = v.y - __bfloat162float(hb.y);
    __nv_bfloat162 lb = __float22bfloat162_rn(lv);
    hi = *(uint32_t*)&hb;
    lo = *(uint32_t*)&lb;
}
__device__ __forceinline__ void mma_bf16(float* d,
    uint32_t a0, uint32_t a1, uint32_t a2, uint32_t a3,
    uint32_t b0, uint32_t b1)
{
    asm volatile(
        "mma.sync.aligned.m16n8k16.row.col.f32.bf16.bf16.f32 "
        "{%0,%1,%2,%3},{%4,%5,%6,%7},{%8,%9},{%0,%1,%2,%3};"
        : "+f"(d[0]), "+f"(d[1]), "+f"(d[2]), "+f"(d[3])
        : "r"(a0), "r"(a1), "r"(a2), "r"(a3), "r"(b0), "r"(b1));
}

__device__ __forceinline__ void cp_copy16(void* dst, const void* src, int n16, int tid){
    uint32_t sbase = (uint32_t)__cvta_generic_to_shared(dst);
    const uint4* s = (const uint4*)src;
    for (int i = tid; i < n16; i += NTHR)
        asm volatile("cp.async.cg.shared.global [%0], [%1], 16;"
                     :: "r"(sbase + i*16), "l"(s + i));
}
#define CP_COMMIT() asm volatile("cp.async.commit_group;" ::: "memory")
#define CP_WAIT0()  asm volatile("cp.async.wait_group 0;" ::: "memory")
#define PAIR_BAR(id) asm volatile("bar.sync %0, 64;" :: "r"(id) : "memory")

// ---------------- one-shot weight packing (uint4 fragment layout) ----------
__global__ void pack_weights(const float* __restrict__ rw1,
                             const float* __restrict__ rw2)
{
    int i = blockIdx.x * blockDim.x + threadIdx.x;
    if (i < NRULES*3*16*128){
        int n    = i & 127;
        int rowq = (i >> 7) & 15;
        int rs   = i >> 11;
        int kt = rowq >> 2, tig = rowq & 3;
        int kp = kt*8 + tig;
        const float* w = rw1 + ((size_t)(rs/3)*K1 + (rs%3)*64) * HID;
        float2 v0, v1;
        v0.x = w[(size_t)(2*kp)   * HID + n];
        v0.y = w[(size_t)(2*kp+1) * HID + n];
        v1.x = w[(size_t)(2*kp+8) * HID + n];
        v1.y = w[(size_t)(2*kp+9) * HID + n];
        uint32_t h0,l0,h1,l1;
        pack_hilo(v0, h0, l0);
        pack_hilo(v1, h1, l1);
        g_w1p4[(size_t)rs*SEG_U4 + rowq*W1P4 + n] = make_uint4(h0,l0,h1,l1);
    } else {
        int q = i - NRULES*3*16*128;
        if (q >= NRULES*32*64) return;
        int n    = q & 63;
        int rowq = (q >> 6) & 31;
        int r    = q >> 11;
        int ktg = rowq >> 2, tig = rowq & 3;
        int kp = ktg*8 + tig;
        const float* w = rw2 + (size_t)r * HID * D_MODEL;
        float2 v0, v1;
        v0.x = w[(size_t)(2*kp)   * D_MODEL + n];
        v0.y = w[(size_t)(2*kp+1) * D_MODEL + n];
        v1.x = w[(size_t)(2*kp+8) * D_MODEL + n];
        v1.y = w[(size_t)(2*kp+9) * D_MODEL + n];
        uint32_t h0,l0,h1,l1;
        pack_hilo(v0, h0, l0);
        pack_hilo(v1, h1, l1);
        g_w2p4[(size_t)r*W2_U4 + rowq*W2P4 + n] = make_uint4(h0,l0,h1,l1);
    }
}

// ---------------- control kernel ----------------
__global__ void control_kernel(
    const float* __restrict__ c,
    const float* __restrict__ sw1, const float* __restrict__ sb1,
    const float* __restrict__ sw2, const float* __restrict__ sb2,
    const float* __restrict__ tw1, const float* __restrict__ tb1,
    const float* __restrict__ tw2, const float* __restrict__ tb2,
    const float* __restrict__ qw1, const float* __restrict__ qb1,
    const float* __restrict__ qw2, const float* __restrict__ qb2)
{
    __shared__ float cs[128], h1[64], h2[32], h3[32];
    int t = threadIdx.x;
    if (t < 128) cs[t] = c[t];
    __syncthreads();
    if (t < 64){
        float a = sb1[t];
        for (int k = 0; k < 128; k++) a += cs[k] * sw1[k*64 + t];
        h1[t] = gelu_exact(a);
    } else if (t < 96){
        int i = t - 64; float a = tb1[i];
        for (int k = 0; k < 128; k++) a += cs[k] * tw1[k*32 + i];
        h2[i] = gelu_exact(a);
    } else {
        int i = t - 96; float a = qb1[i];
        for (int k = 0; k < 128; k++) a += cs[k] * qw1[k*32 + i];
        h3[i] = gelu_exact(a);
    }
    __syncthreads();
    if (t == 0){
        float l[4], mx = -1e30f;
        for (int r = 0; r < 4; r++){
            float a = sb2[r];
            for (int i = 0; i < 64; i++) a += h1[i] * sw2[i*4 + r];
            l[r] = a; mx = fmaxf(mx, a);
        }
        float s = 0.f;
        for (int r = 0; r < 4; r++){ l[r] = expf(l[r]-mx); s += l[r]; }
        for (int r = 0; r < 4; r++) g_rw[r] = l[r]/s;
    }
    if (t == 1){
        float l[7], mx = -1e30f;
        for (int q = 0; q < 7; q++){
            float a = tb2[q];
            for (int i = 0; i < 32; i++) a += h2[i] * tw2[i*7 + q];
            l[q] = a; mx = fmaxf(mx, a);
        }
        float s = 0.f;
        for (int q = 0; q < 7; q++){ l[q] = expf(l[q]-mx); s += l[q]; }
        float nf = 0.f;
        for (int q = 0; q < 7; q++) nf += (l[q]/s) * (float)(q+2);
        int n = (int)(nf + 0.5f);
        g_nev = n < 2 ? 2 : (n > 8 ? 8 : n);
    }
    if (t == 2){
        float v = qb2[0];
        for (int i = 0; i < 32; i++) v += h3[i] * qw2[i];
        g_alpha = 0.1f + 0.8f / (1.0f + expf(-v));
    }
}

// one GEMM1 segment: 4 k-tiles x 8 n-tiles x 3 terms (B via LDS.128)
__device__ __forceinline__ void gemm1_seg(float acc[8][4], const uint4* wseg,
    const uint2* apr, const uint2* bpr, int half, int g, int tig)
{
    #pragma unroll
    for (int kt = 0; kt < 4; kt++){
        const int kp = kt*8 + tig;
        uint2 A0 = apr[kp],   A1 = bpr[kp];
        uint2 A2 = apr[kp+4], A3 = bpr[kp+4];
        const uint4* br = wseg + (size_t)(kt*4 + tig)*W1P4;
        #pragma unroll
        for (int ntl = 0; ntl < 8; ntl++){
            uint4 qv = br[(half*8 + ntl)*8 + g];
            mma_bf16(acc[ntl], A0.x,A1.x,A2.x,A3.x, qv.x, qv.z);
            mma_bf16(acc[ntl], A0.y,A1.y,A2.y,A3.y, qv.x, qv.z);
            mma_bf16(acc[ntl], A0.x,A1.x,A2.x,A3.x, qv.y, qv.w);
        }
    }
}

// ---------------- evolve step (64 tokens/CTA, 2 CTAs/SM) ----------------
__global__ void __launch_bounds__(NTHR, 2)
step_kernel(const float* __restrict__ cells_in,
            const float* __restrict__ rb1, const float* __restrict__ rb2,
            int j)
{
    if (j >= g_nev) return;

    extern __shared__ char smc[];
    uint2*  cp  = (uint2*)smc;
    uint4*  r0  = (uint4*)(smc + OFF_R0B);
    uint4*  r1  = (uint4*)(smc + OFF_R1B);
    float4* xb  = (float4*)(smc + OFF_XCHB);

    const float* src = (j == 0) ? cells_in : ((j & 1) ? g_buf0 : g_buf1);
    float*       dst = (j & 1) ? g_buf1 : g_buf0;

    const int tid  = threadIdx.x;
    const int w    = tid >> 5;
    const int lane = tid & 31;
    const int g    = lane >> 2;
    const int tig  = lane & 3;
    const int half = w & 1;           // n-half within pair
    const int wp   = w >> 1;          // pair id 0..3
    const int m0   = wp * 16;

    const int brow = blockIdx.x >> 7;           // 128 tiles per batch row
    const int t0   = (blockIdx.x & 127) << 6;   // 64-token tile
    const float* rowbase = src + (size_t)brow * TT * D_MODEL;

    // prefetch rule0 seg0 -> R0 while building the cells tile
    cp_copy16(r0, g_w1p4, SEG_U4, tid);
    CP_COMMIT();

    // packed cells halo: rows t0-1 .. t0+64 (66 rows x 32 kp)
    for (int i = tid; i < 66*32; i += NTHR){
        int row = i >> 5, kp = i & 31;
        int t = (t0 - 1 + row) & (TT - 1);
        float2 v = *(const float2*)(rowbase + (size_t)t * D_MODEL + 2*kp);
        uint32_t hi, lo;
        pack_hilo(v, hi, lo);
        cp[row*CP2P + kp] = make_uint2(hi, lo);
    }
    CP_WAIT0();
    __syncthreads();

    float outa[16];
    #pragma unroll
    for (int i = 0; i < 16; i++) outa[i] = 0.0f;

    for (int r = 0; r < NRULES; r++){
        const uint2* apr0 = cp + (size_t)(m0 + 1 + g) * CP2P;   // cells[t]
        const uint2* apr1 = cp + (size_t)(m0 + 0 + g) * CP2P;   // cells[t-1]
        const uint2* apr2 = cp + (size_t)(m0 + 2 + g) * CP2P;   // cells[t+1]

        float acc[8][4];
        #pragma unroll
        for (int a = 0; a < 8; a++){
            acc[a][0]=0.f; acc[a][1]=0.f; acc[a][2]=0.f; acc[a][3]=0.f;
        }

        // seg0 already in R0. prefetch seg1 -> R1; compute seg0
        cp_copy16(r1, g_w1p4 + (size_t)(r*3+1)*SEG_U4, SEG_U4, tid);
        CP_COMMIT();
        gemm1_seg(acc, r0, apr0, apr0 + 8*CP2P, half, g, tig);
        CP_WAIT0();
        __syncthreads();

        // prefetch seg2 -> R0; compute seg1
        cp_copy16(r0, g_w1p4 + (size_t)(r*3+2)*SEG_U4, SEG_U4, tid);
        CP_COMMIT();
        gemm1_seg(acc, r1, apr1, apr1 + 8*CP2P, half, g, tig);
        CP_WAIT0();
        __syncthreads();

        // prefetch W2 -> R1; compute seg2
        cp_copy16(r1, g_w2p4 + (size_t)r*W2_U4, W2_U4, tid);
        CP_COMMIT();
        gemm1_seg(acc, r0, apr2, apr2 + 8*CP2P, half, g, tig);
        CP_WAIT0();
        __syncthreads();

        // prefetch next rule seg0 -> R0 (overlaps epi+GEMM2)
        if (r < NRULES-1){
            cp_copy16(r0, g_w1p4 + (size_t)((r+1)*3)*SEG_U4, SEG_U4, tid);
            CP_COMMIT();
        }

        // epi1 in registers: h = gelu(C1+b1) -> GEMM2 A fragments
        uint32_t fh[4][4], fl[4][4];
        #pragma unroll
        for (int ktl = 0; ktl < 4; ktl++){
            #pragma unroll
            for (int sub = 0; sub < 2; sub++){
                int ntl = 2*ktl + sub;
                int c   = (half*8 + ntl)*8 + 2*tig;
                const float2 bb = __ldg((const float2*)(rb1 + r*HID + c));
                float2 va, vb;
                va.x = gelu_fast(acc[ntl][0] + bb.x);
                va.y = gelu_fast(acc[ntl][1] + bb.y);
                vb.x = gelu_fast(acc[ntl][2] + bb.x);
                vb.y = gelu_fast(acc[ntl][3] + bb.y);
                pack_hilo(va, fh[ktl][sub*2],   fl[ktl][sub*2]);
                pack_hilo(vb, fh[ktl][sub*2+1], fl[ktl][sub*2+1]);
            }
        }

        // GEMM2: k-chunks half*4..+3, all 8 n-tiles (W2 in R1)
        float acc2[8][4];
        #pragma unroll
        for (int a = 0; a < 8; a++){
            acc2[a][0]=0.f; acc2[a][1]=0.f; acc2[a][2]=0.f; acc2[a][3]=0.f;
        }
        #pragma unroll
        for (int ktl = 0; ktl < 4; ktl++){
            const uint4* br = r1 + (size_t)((half*4+ktl)*4 + tig)*W2P4;
            #pragma unroll
            for (int nt = 0; nt < 8; nt++){
                uint4 qv = br[nt*8 + g];
                mma_bf16(acc2[nt], fh[ktl][0],fh[ktl][1],fh[ktl][2],fh[ktl][3], qv.x, qv.z);
                mma_bf16(acc2[nt], fl[ktl][0],fl[ktl][1],fl[ktl][2],fl[ktl][3], qv.x, qv.z);
                mma_bf16(acc2[nt], fh[ktl][0],fh[ktl][1],fh[ktl][2],fh[ktl][3], qv.y, qv.w);
            }
        }

        // exchange partner's tiles via dedicated xchg buffer + pair barrier
        {
            const int sbase = (wp*2 + half)*4;
            const int pnt   = (1 - half)*4;
            #pragma unroll
            for (int q = 0; q < 4; q++)
                xb[(sbase + q)*32 + lane] = make_float4(
                    acc2[pnt+q][0], acc2[pnt+q][1], acc2[pnt+q][2], acc2[pnt+q][3]);
        }
        PAIR_BAR(1 + wp);

        // finalize: own partial + partner partial -> tanh -> outa
        {
            const int pbase = (wp*2 + (1 - half))*4;
            const int ont   = half*4;
            const float rr = g_rw[r];
            #pragma unroll
            for (int q = 0; q < 4; q++){
                float4 pp = xb[(pbase + q)*32 + lane];
                int c = (ont + q)*8 + 2*tig;
                const float2 bb = __ldg((const float2*)(rb2 + r*D_MODEL + c));
                outa[q*4+0] += rr * tanh_fast(acc2[ont+q][0] + pp.x + bb.x);
                outa[q*4+1] += rr * tanh_fast(acc2[ont+q][1] + pp.y + bb.y);
                outa[q*4+2] += rr * tanh_fast(acc2[ont+q][2] + pp.z + bb.x);
                outa[q*4+3] += rr * tanh_fast(acc2[ont+q][3] + pp.w + bb.y);
            }
        }
        PAIR_BAR(1 + wp);      // xchg slot reusable next rule
        CP_WAIT0();
        __syncthreads();       // next seg0 staged; R1 free
    }

    // residual mix + store
    {
        const float al = g_alpha, om = 1.0f - al;
        const float* sra = src + ((size_t)brow*TT + t0 + m0 + g) * D_MODEL;
        const float* srb = src + ((size_t)brow*TT + t0 + m0 + g + 8) * D_MODEL;
        float* da = dst + ((size_t)brow*TT + t0 + m0 + g) * D_MODEL;
        float* db = dst + ((size_t)brow*TT + t0 + m0 + g + 8) * D_MODEL;
        #pragma unroll
        for (int q = 0; q < 4; q++){
            int c = (half*4 + q)*8 + 2*tig;
            float2 cva = __ldg((const float2*)(sra + c));
            float2 cvb = __ldg((const float2*)(srb + c));
            float2 oa, ob;
            oa.x = al*cva.x + om*outa[q*4+0];
            oa.y = al*cva.y + om*outa[q*4+1];
            ob.x = al*cvb.x + om*outa[q*4+2];
            ob.y = al*cvb.y + om*outa[q*4+3];
            *(float2*)(da + c) = oa;
            *(float2*)(db + c) = ob;
        }
    }
}

// ---------------- final LayerNorm ----------------
__global__ void __launch_bounds__(256)
ln_kernel(const float* __restrict__ g, const float* __restrict__ b,
          float* __restrict__ out)
{
    const float* src = ((g_nev - 1) & 1) ? g_buf1 : g_buf0;
    int tok  = blockIdx.x * 8 + (threadIdx.x >> 5);
    int lane = threadIdx.x & 31;
    float2 v = ((const float2*)(src + (size_t)tok * D_MODEL))[lane];
    float s = v.x + v.y;
    #pragma unroll
    for (int o = 16; o; o >>= 1) s += __shfl_xor_sync(0xffffffffu, s, o);
    float mu = s * (1.0f/64.0f);
    float dx = v.x - mu, dy = v.y - mu;
    float ss = dx*dx + dy*dy;
    #pragma unroll
    for (int o = 16; o; o >>= 1) ss += __shfl_xor_sync(0xffffffffu, ss, o);
    float rstd = rsqrtf(ss * (1.0f/64.0f) + LN_EPS);
    float2 gg = ((const float2*)g)[lane];
    float2 bb = ((const float2*)b)[lane];
    float2 ov;
    ov.x = dx * rstd * gg.x + bb.x;
    ov.y = dy * rstd * gg.y + bb.y;
    ((float2*)(out + (size_t)tok * D_MODEL))[lane] = ov;
}

// ---------------- launch ----------------
extern "C" void kernel_launch(void* const* d_in, const int* in_sizes, int n_in,
                              void* d_out, int out_size)
{
    const float* cells = (const float*)d_in[0];
    cudaFuncSetAttribute(step_kernel,
                         cudaFuncAttributeMaxDynamicSharedMemorySize, SMEM_BYTES);

    control_kernel<<<1, 128>>>((const float*)d_in[1],
        (const float*)d_in[6],  (const float*)d_in[7],
        (const float*)d_in[8],  (const float*)d_in[9],
        (const float*)d_in[10], (const float*)d_in[11],
        (const float*)d_in[12], (const float*)d_in[13],
        (const float*)d_in[14], (const float*)d_in[15],
        (const float*)d_in[16], (const float*)d_in[17]);

    pack_weights<<<(NRULES*3*16*128 + NRULES*32*64 + 255)/256, 256>>>(
        (const float*)d_in[2], (const float*)d_in[4]);

    for (int j = 0; j < 8; j++)
        step_kernel<<<NBLK, NTHR, SMEM_BYTES>>>(cells,
            (const float*)d_in[3], (const float*)d_in[5], j);

    ln_kernel<<<NTOK/8, 256>>>((const float*)d_in[18], (const float*)d_in[19],
                               (float*)d_out);
}

// round 15
// speedup vs baseline: 1.6479x; 1.4937x over previous
#include <cuda_runtime.h>
#include <cuda_fp16.h>
#include <cstdint>
#include <math.h>

#define D_MODEL 64
#define HID     128
#define NRULES  4
#define K1      192
#define TT      8192
#define NTOK    (32*TT)
#define NBLK    (NTOK/64)          // 4096 CTAs, 64 tokens each
#define NTHR    256
#define LN_EPS  1e-5f

#define CP2P 36                    // cells pitch (uint2), conflict-free LDS.64
#define W1P2 132                   // W1 pitch (uint2), ≡4 mod 16 -> conflict-free LDS.64
#define W2P2 68                    // W2 pitch (uint2), ≡4 mod 16

#define SEG_BYTES (16*W1P2*8)      // 16896
#define SEG_U4    (SEG_BYTES/16)   // 1056
#define W2_BYTES  (32*W2P2*8)      // 17408
#define W2_U4     (W2_BYTES/16)    // 1088

// smem layout (bytes): cells 66*36*8 = 19008 | R0 17408 | R1 17408 | xchg 16384
#define OFF_R0B  19008
#define OFF_R1B  (OFF_R0B + 17408)         // 36416
#define OFF_XCHB (OFF_R1B + 17408)         // 53824
#define SMEM_BYTES (OFF_XCHB + 16384)      // 70208  (x2 CTAs = 140416)

__device__ float g_rw[4];
__device__ float g_alpha;
__device__ int   g_nev;
__device__ float g_buf0[(size_t)NTOK*D_MODEL];
__device__ float g_buf1[(size_t)NTOK*D_MODEL];
// pre-packed fp16 weights (single precision), uint2 B-fragment layout
__device__ __align__(16) uint2 g_w1p[NRULES*3*16*W1P2];
__device__ __align__(16) uint2 g_w2p[NRULES*32*W2P2];

__device__ __forceinline__ float gelu_exact(float x){
    return 0.5f * x * (1.0f + erff(x * 0.7071067811865475f));
}
// A&S 7.1.26 erf (abs err <= 1.5e-7)
__device__ __forceinline__ float gelu_fast(float x){
    float z  = 0.70710678118f * x;
    float az = fabsf(z);
    float t  = __fdividef(1.0f, fmaf(0.3275911f, az, 1.0f));
    float p  = t*fmaf(t, fmaf(t, fmaf(t, fmaf(t, 1.061405429f, -1.453152027f),
                1.421413741f), -0.284496736f), 0.254829592f);
    float e  = __expf(-z*z);
    float er = copysignf(fmaf(-p, e, 1.0f), z);
    return 0.5f * x * (1.0f + er);
}
__device__ __forceinline__ float tanh_fast(float x){
    float e = __expf(2.0f*x);
    return 1.0f - __fdividef(2.0f, e + 1.0f);
}
// split float pair into fp16x2 hi and fp16x2 lo packs
__device__ __forceinline__ void pack_hilo(float2 v, uint32_t& hi, uint32_t& lo){
    __half2 hb = __float22half2_rn(v);
    float2 lv;
    lv.x = v.x - __half2float(__low2half(hb));
    lv.y = v.y - __half2float(__high2half(hb));
    __half2 lb = __float22half2_rn(lv);
    hi = *(uint32_t*)&hb;
    lo = *(uint32_t*)&lb;
}
// single-precision fp16 pack (weights)
__device__ __forceinline__ uint32_t pack_f16(float2 v){
    __half2 hb = __float22half2_rn(v);
    return *(uint32_t*)&hb;
}
__device__ __forceinline__ void mma_f16(float* d,
    uint32_t a0, uint32_t a1, uint32_t a2, uint32_t a3,
    uint32_t b0, uint32_t b1)
{
    asm volatile(
        "mma.sync.aligned.m16n8k16.row.col.f32.f16.f16.f32 "
        "{%0,%1,%2,%3},{%4,%5,%6,%7},{%8,%9},{%0,%1,%2,%3};"
        : "+f"(d[0]), "+f"(d[1]), "+f"(d[2]), "+f"(d[3])
        : "r"(a0), "r"(a1), "r"(a2), "r"(a3), "r"(b0), "r"(b1));
}

__device__ __forceinline__ void cp_copy16(void* dst, const void* src, int n16, int tid){
    uint32_t sbase = (uint32_t)__cvta_generic_to_shared(dst);
    const uint4* s = (const uint4*)src;
    for (int i = tid; i < n16; i += NTHR)
        asm volatile("cp.async.cg.shared.global [%0], [%1], 16;"
                     :: "r"(sbase + i*16), "l"(s + i));
}
#define CP_COMMIT() asm volatile("cp.async.commit_group;" ::: "memory")
#define CP_WAIT0()  asm volatile("cp.async.wait_group 0;" ::: "memory")
#define PAIR_BAR(id) asm volatile("bar.sync %0, 64;" :: "r"(id) : "memory")

// ---------------- one-shot weight packing (uint2 fp16 fragment layout) -----
// entry[(kt*4+tig)*pitch + n] = { h2(w[2kp],w[2kp+1]), h2(w[2kp+8],w[2kp+9]) },
// kp = kt*8 + tig.
__global__ void pack_weights(const float* __restrict__ rw1,
                             const float* __restrict__ rw2)
{
    int i = blockIdx.x * blockDim.x + threadIdx.x;
    if (i < NRULES*3*16*128){
        int n    = i & 127;
        int rowq = (i >> 7) & 15;
        int rs   = i >> 11;
        int kt = rowq >> 2, tig = rowq & 3;
        int kp = kt*8 + tig;
        const float* w = rw1 + ((size_t)(rs/3)*K1 + (rs%3)*64) * HID;
        float2 v0, v1;
        v0.x = w[(size_t)(2*kp)   * HID + n];
        v0.y = w[(size_t)(2*kp+1) * HID + n];
        v1.x = w[(size_t)(2*kp+8) * HID + n];
        v1.y = w[(size_t)(2*kp+9) * HID + n];
        g_w1p[(size_t)rs*16*W1P2 + rowq*W1P2 + n] =
            make_uint2(pack_f16(v0), pack_f16(v1));
    } else {
        int q = i - NRULES*3*16*128;
        if (q >= NRULES*32*64) return;
        int n    = q & 63;
        int rowq = (q >> 6) & 31;
        int r    = q >> 11;
        int ktg = rowq >> 2, tig = rowq & 3;
        int kp = ktg*8 + tig;
        const float* w = rw2 + (size_t)r * HID * D_MODEL;
        float2 v0, v1;
        v0.x = w[(size_t)(2*kp)   * D_MODEL + n];
        v0.y = w[(size_t)(2*kp+1) * D_MODEL + n];
        v1.x = w[(size_t)(2*kp+8) * D_MODEL + n];
        v1.y = w[(size_t)(2*kp+9) * D_MODEL + n];
        g_w2p[(size_t)r*32*W2P2 + rowq*W2P2 + n] =
            make_uint2(pack_f16(v0), pack_f16(v1));
    }
}

// ---------------- control kernel ----------------
__global__ void control_kernel(
    const float* __restrict__ c,
    const float* __restrict__ sw1, const float* __restrict__ sb1,
    const float* __restrict__ sw2, const float* __restrict__ sb2,
    const float* __restrict__ tw1, const float* __restrict__ tb1,
    const float* __restrict__ tw2, const float* __restrict__ tb2,
    const float* __restrict__ qw1, const float* __restrict__ qb1,
    const float* __restrict__ qw2, const float* __restrict__ qb2)
{
    __shared__ float cs[128], h1[64], h2[32], h3[32];
    int t = threadIdx.x;
    if (t < 128) cs[t] = c[t];
    __syncthreads();
    if (t < 64){
        float a = sb1[t];
        for (int k = 0; k < 128; k++) a += cs[k] * sw1[k*64 + t];
        h1[t] = gelu_exact(a);
    } else if (t < 96){
        int i = t - 64; float a = tb1[i];
        for (int k = 0; k < 128; k++) a += cs[k] * tw1[k*32 + i];
        h2[i] = gelu_exact(a);
    } else {
        int i = t - 96; float a = qb1[i];
        for (int k = 0; k < 128; k++) a += cs[k] * qw1[k*32 + i];
        h3[i] = gelu_exact(a);
    }
    __syncthreads();
    if (t == 0){
        float l[4], mx = -1e30f;
        for (int r = 0; r < 4; r++){
            float a = sb2[r];
            for (int i = 0; i < 64; i++) a += h1[i] * sw2[i*4 + r];
            l[r] = a; mx = fmaxf(mx, a);
        }
        float s = 0.f;
        for (int r = 0; r < 4; r++){ l[r] = expf(l[r]-mx); s += l[r]; }
        for (int r = 0; r < 4; r++) g_rw[r] = l[r]/s;
    }
    if (t == 1){
        float l[7], mx = -1e30f;
        for (int q = 0; q < 7; q++){
            float a = tb2[q];
            for (int i = 0; i < 32; i++) a += h2[i] * tw2[i*7 + q];
            l[q] = a; mx = fmaxf(mx, a);
        }
        float s = 0.f;
        for (int q = 0; q < 7; q++){ l[q] = expf(l[q]-mx); s += l[q]; }
        float nf = 0.f;
        for (int q = 0; q < 7; q++) nf += (l[q]/s) * (float)(q+2);
        int n = (int)(nf + 0.5f);
        g_nev = n < 2 ? 2 : (n > 8 ? 8 : n);
    }
    if (t == 2){
        float v = qb2[0];
        for (int i = 0; i < 32; i++) v += h3[i] * qw2[i];
        g_alpha = 0.1f + 0.8f / (1.0f + expf(-v));
    }
}

// one GEMM1 segment: 4 k-tiles x 8 n-tiles x 2 terms (B via LDS.64)
__device__ __forceinline__ void gemm1_seg(float acc[8][4], const uint2* wseg,
    const uint2* apr, const uint2* bpr, int half, int g, int tig)
{
    #pragma unroll
    for (int kt = 0; kt < 4; kt++){
        const int kp = kt*8 + tig;
        uint2 A0 = apr[kp],   A1 = bpr[kp];
        uint2 A2 = apr[kp+4], A3 = bpr[kp+4];
        const uint2* br = wseg + (size_t)(kt*4 + tig)*W1P2;
        #pragma unroll
        for (int ntl = 0; ntl < 8; ntl++){
            uint2 qv = br[(half*8 + ntl)*8 + g];
            mma_f16(acc[ntl], A0.x,A1.x,A2.x,A3.x, qv.x, qv.y);
            mma_f16(acc[ntl], A0.y,A1.y,A2.y,A3.y, qv.x, qv.y);
        }
    }
}

// ---------------- evolve step (64 tokens/CTA, 2 CTAs/SM) ----------------
__global__ void __launch_bounds__(NTHR, 2)
step_kernel(const float* __restrict__ cells_in,
            const float* __restrict__ rb1, const float* __restrict__ rb2,
            int j)
{
    if (j >= g_nev) return;

    extern __shared__ char smc[];
    uint2*  cp  = (uint2*)smc;
    uint2*  r0  = (uint2*)(smc + OFF_R0B);
    uint2*  r1  = (uint2*)(smc + OFF_R1B);
    float4* xb  = (float4*)(smc + OFF_XCHB);

    const float* src = (j == 0) ? cells_in : ((j & 1) ? g_buf0 : g_buf1);
    float*       dst = (j & 1) ? g_buf1 : g_buf0;

    const int tid  = threadIdx.x;
    const int w    = tid >> 5;
    const int lane = tid & 31;
    const int g    = lane >> 2;
    const int tig  = lane & 3;
    const int half = w & 1;           // n-half within pair
    const int wp   = w >> 1;          // pair id 0..3
    const int m0   = wp * 16;

    const int brow = blockIdx.x >> 7;
    const int t0   = (blockIdx.x & 127) << 6;
    const float* rowbase = src + (size_t)brow * TT * D_MODEL;

    // prefetch rule0 seg0 -> R0 while building the cells tile
    cp_copy16(r0, g_w1p, SEG_U4, tid);
    CP_COMMIT();

    // packed fp16 hi/lo cells halo: rows t0-1 .. t0+64
    for (int i = tid; i < 66*32; i += NTHR){
        int row = i >> 5, kp = i & 31;
        int t = (t0 - 1 + row) & (TT - 1);
        float2 v = *(const float2*)(rowbase + (size_t)t * D_MODEL + 2*kp);
        uint32_t hi, lo;
        pack_hilo(v, hi, lo);
        cp[row*CP2P + kp] = make_uint2(hi, lo);
    }
    CP_WAIT0();
    __syncthreads();

    float outa[16];
    #pragma unroll
    for (int i = 0; i < 16; i++) outa[i] = 0.0f;

    for (int r = 0; r < NRULES; r++){
        const uint2* apr0 = cp + (size_t)(m0 + 1 + g) * CP2P;   // cells[t]
        const uint2* apr1 = cp + (size_t)(m0 + 0 + g) * CP2P;   // cells[t-1]
        const uint2* apr2 = cp + (size_t)(m0 + 2 + g) * CP2P;   // cells[t+1]

        float acc[8][4];
        #pragma unroll
        for (int a = 0; a < 8; a++){
            acc[a][0]=0.f; acc[a][1]=0.f; acc[a][2]=0.f; acc[a][3]=0.f;
        }

        // seg0 in R0. prefetch seg1 -> R1; compute seg0
        cp_copy16(r1, g_w1p + (size_t)(r*3+1)*16*W1P2, SEG_U4, tid);
        CP_COMMIT();
        gemm1_seg(acc, r0, apr0, apr0 + 8*CP2P, half, g, tig);
        CP_WAIT0();
        __syncthreads();

        // prefetch seg2 -> R0; compute seg1
        cp_copy16(r0, g_w1p + (size_t)(r*3+2)*16*W1P2, SEG_U4, tid);
        CP_COMMIT();
        gemm1_seg(acc, r1, apr1, apr1 + 8*CP2P, half, g, tig);
        CP_WAIT0();
        __syncthreads();

        // prefetch W2 -> R1; compute seg2
        cp_copy16(r1, g_w2p + (size_t)r*32*W2P2, W2_U4, tid);
        CP_COMMIT();
        gemm1_seg(acc, r0, apr2, apr2 + 8*CP2P, half, g, tig);
        CP_WAIT0();
        __syncthreads();

        // prefetch next rule seg0 -> R0 (overlaps epi+GEMM2)
        if (r < NRULES-1){
            cp_copy16(r0, g_w1p + (size_t)((r+1)*3)*16*W1P2, SEG_U4, tid);
            CP_COMMIT();
        }

        // epi1 in registers: h = gelu(C1+b1) -> GEMM2 A fragments (fp16 hi/lo)
        uint32_t fh[4][4], fl[4][4];
        #pragma unroll
        for (int ktl = 0; ktl < 4; ktl++){
            #pragma unroll
            for (int sub = 0; sub < 2; sub++){
                int ntl = 2*ktl + sub;
                int c   = (half*8 + ntl)*8 + 2*tig;
                const float2 bb = __ldg((const float2*)(rb1 + r*HID + c));
                float2 va, vb;
                va.x = gelu_fast(acc[ntl][0] + bb.x);
                va.y = gelu_fast(acc[ntl][1] + bb.y);
                vb.x = gelu_fast(acc[ntl][2] + bb.x);
                vb.y = gelu_fast(acc[ntl][3] + bb.y);
                pack_hilo(va, fh[ktl][sub*2],   fl[ktl][sub*2]);
                pack_hilo(vb, fh[ktl][sub*2+1], fl[ktl][sub*2+1]);
            }
        }

        // GEMM2: k-chunks half*4..+3, all 8 n-tiles (W2 in R1), 2 terms
        float acc2[8][4];
        #pragma unroll
        for (int a = 0; a < 8; a++){
            acc2[a][0]=0.f; acc2[a][1]=0.f; acc2[a][2]=0.f; acc2[a][3]=0.f;
        }
        #pragma unroll
        for (int ktl = 0; ktl < 4; ktl++){
            const uint2* br = r1 + (size_t)((half*4+ktl)*4 + tig)*W2P2;
            #pragma unroll
            for (int nt = 0; nt < 8; nt++){
                uint2 qv = br[nt*8 + g];
                mma_f16(acc2[nt], fh[ktl][0],fh[ktl][1],fh[ktl][2],fh[ktl][3], qv.x, qv.y);
                mma_f16(acc2[nt], fl[ktl][0],fl[ktl][1],fl[ktl][2],fl[ktl][3], qv.x, qv.y);
            }
        }

        // exchange partner's tiles via dedicated xchg buffer + pair barrier
        {
            const int sbase = (wp*2 + half)*4;
            const int pnt   = (1 - half)*4;
            #pragma unroll
            for (int q = 0; q < 4; q++)
                xb[(sbase + q)*32 + lane] = make_float4(
                    acc2[pnt+q][0], acc2[pnt+q][1], acc2[pnt+q][2], acc2[pnt+q][3]);
        }
        PAIR_BAR(1 + wp);

        // finalize: own partial + partner partial -> tanh -> outa
        {
            const int pbase = (wp*2 + (1 - half))*4;
            const int ont   = half*4;
            const float rr = g_rw[r];
            #pragma unroll
            for (int q = 0; q < 4; q++){
                float4 pp = xb[(pbase + q)*32 + lane];
                int c = (ont + q)*8 + 2*tig;
                const float2 bb = __ldg((const float2*)(rb2 + r*D_MODEL + c));
                outa[q*4+0] += rr * tanh_fast(acc2[ont+q][0] + pp.x + bb.x);
                outa[q*4+1] += rr * tanh_fast(acc2[ont+q][1] + pp.y + bb.y);
                outa[q*4+2] += rr * tanh_fast(acc2[ont+q][2] + pp.z + bb.x);
                outa[q*4+3] += rr * tanh_fast(acc2[ont+q][3] + pp.w + bb.y);
            }
        }
        PAIR_BAR(1 + wp);      // xchg slot reusable next rule
        CP_WAIT0();
        __syncthreads();       // next seg0 staged; R1 free
    }

    // residual mix + store
    {
        const float al = g_alpha, om = 1.0f - al;
        const float* sra = src + ((size_t)brow*TT + t0 + m0 + g) * D_MODEL;
        const float* srb = src + ((size_t)brow*TT + t0 + m0 + g + 8) * D_MODEL;
        float* da = dst + ((size_t)brow*TT + t0 + m0 + g) * D_MODEL;
        float* db = dst + ((size_t)brow*TT + t0 + m0 + g + 8) * D_MODEL;
        #pragma unroll
        for (int q = 0; q < 4; q++){
            int c = (half*4 + q)*8 + 2*tig;
            float2 cva = __ldg((const float2*)(sra + c));
            float2 cvb = __ldg((const float2*)(srb + c));
            float2 oa, ob;
            oa.x = al*cva.x + om*outa[q*4+0];
            oa.y = al*cva.y + om*outa[q*4+1];
            ob.x = al*cvb.x + om*outa[q*4+2];
            ob.y = al*cvb.y + om*outa[q*4+3];
            *(float2*)(da + c) = oa;
            *(float2*)(db + c) = ob;
        }
    }
}

// ---------------- final LayerNorm ----------------
__global__ void __launch_bounds__(256)
ln_kernel(const float* __restrict__ g, const float* __restrict__ b,
          float* __restrict__ out)
{
    const float* src = ((g_nev - 1) & 1) ? g_buf1 : g_buf0;
    int tok  = blockIdx.x * 8 + (threadIdx.x >> 5);
    int lane = threadIdx.x & 31;
    float2 v = ((const float2*)(src + (size_t)tok * D_MODEL))[lane];
    float s = v.x + v.y;
    #pragma unroll
    for (int o = 16; o; o >>= 1) s += __shfl_xor_sync(0xffffffffu, s, o);
    float mu = s * (1.0f/64.0f);
    float dx = v.x - mu, dy = v.y - mu;
    float ss = dx*dx + dy*dy;
    #pragma unroll
    for (int o = 16; o; o >>= 1) ss += __shfl_xor_sync(0xffffffffu, ss, o);
    float rstd = rsqrtf(ss * (1.0f/64.0f) + LN_EPS);
    float2 gg = ((const float2*)g)[lane];
    float2 bb = ((const float2*)b)[lane];
    float2 ov;
    ov.x = dx * rstd * gg.x + bb.x;
    ov.y = dy * rstd * gg.y + bb.y;
    ((float2*)(out + (size_t)tok * D_MODEL))[lane] = ov;
}

// ---------------- launch ----------------
extern "C" void kernel_launch(void* const* d_in, const int* in_sizes, int n_in,
                              void* d_out, int out_size)
{
    const float* cells = (const float*)d_in[0];
    cudaFuncSetAttribute(step_kernel,
                         cudaFuncAttributeMaxDynamicSharedMemorySize, SMEM_BYTES);

    control_kernel<<<1, 128>>>((const float*)d_in[1],
        (const float*)d_in[6],  (const float*)d_in[7],
        (const float*)d_in[8],  (const float*)d_in[9],
        (const float*)d_in[10], (const float*)d_in[11],
        (const float*)d_in[12], (const float*)d_in[13],
        (const float*)d_in[14], (const float*)d_in[15],
        (const float*)d_in[16], (const float*)d_in[17]);

    pack_weights<<<(NRULES*3*16*128 + NRULES*32*64 + 255)/256, 256>>>(
        (const float*)d_in[2], (const float*)d_in[4]);

    for (int j = 0; j < 8; j++)
        step_kernel<<<NBLK, NTHR, SMEM_BYTES>>>(cells,
            (const float*)d_in[3], (const float*)d_in[5], j);

    ln_kernel<<<NTOK/8, 256>>>((const float*)d_in[18], (const float*)d_in[19],
                               (float*)d_out);
}

// round 16
// speedup vs baseline: 2.1741x; 1.3193x over previous
#include <cuda_runtime.h>
#include <cuda_fp16.h>
#include <cstdint>
#include <math.h>

#define D_MODEL 64
#define HID     128
#define NRULES  4
#define K1      192
#define TT      8192
#define NTOK    (32*TT)
#define NBLK    (NTOK/64)          // 4096 CTAs, 64 tokens each
#define NTHR    256
#define LN_EPS  1e-5f

#define CPF  20                    // cells fragment pitch (uint2), (4g+tig) mod16 bijective
#define W1P4 66                    // W1 pitch (uint4), ≡2 mod 8 -> conflict-free LDS.128
#define W2P4 34                    // W2 pitch (uint4), ≡2 mod 8

#define SEG_BYTES (16*W1P4*16)     // 16896
#define SEG_U4    (SEG_BYTES/16)   // 1056
#define W2_BYTES  (32*W2P4*16)     // 17408
#define W2_U4     (W2_BYTES/16)    // 1088

// smem layout (bytes): cells 66*20*8 = 10560 | R0 16896 | R1 17408 | xchg 16384
#define OFF_R0B  10560
#define OFF_R1B  (OFF_R0B + SEG_BYTES)     // 27456
#define OFF_XCHB (OFF_R1B + W2_BYTES)      // 44864
#define SMEM_BYTES (OFF_XCHB + 16384)      // 61248  (x2 CTAs = 122496)

__device__ float g_rw[4];
__device__ float g_alpha;
__device__ int   g_nev;
__device__ float g_buf0[(size_t)NTOK*D_MODEL];
__device__ float g_buf1[(size_t)NTOK*D_MODEL];
// pre-packed fp16 weights, uint4 n-pair fragment layout
__device__ __align__(16) uint4 g_w1p[NRULES*3*16*W1P4];
__device__ __align__(16) uint4 g_w2p[NRULES*32*W2P4];

__device__ __forceinline__ float gelu_exact(float x){
    return 0.5f * x * (1.0f + erff(x * 0.7071067811865475f));
}
// A&S 7.1.26 erf (abs err <= 1.5e-7)
__device__ __forceinline__ float gelu_fast(float x){
    float z  = 0.70710678118f * x;
    float az = fabsf(z);
    float t  = __fdividef(1.0f, fmaf(0.3275911f, az, 1.0f));
    float p  = t*fmaf(t, fmaf(t, fmaf(t, fmaf(t, 1.061405429f, -1.453152027f),
                1.421413741f), -0.284496736f), 0.254829592f);
    float e  = __expf(-z*z);
    float er = copysignf(fmaf(-p, e, 1.0f), z);
    return 0.5f * x * (1.0f + er);
}
__device__ __forceinline__ float tanh_fast(float x){
    float e = __expf(2.0f*x);
    return 1.0f - __fdividef(2.0f, e + 1.0f);
}
__device__ __forceinline__ uint32_t pack_f16(float2 v){
    __half2 hb = __float22half2_rn(v);
    return *(uint32_t*)&hb;
}
__device__ __forceinline__ void mma_f16(float* d,
    uint32_t a0, uint32_t a1, uint32_t a2, uint32_t a3,
    uint32_t b0, uint32_t b1)
{
    asm volatile(
        "mma.sync.aligned.m16n8k16.row.col.f32.f16.f16.f32 "
        "{%0,%1,%2,%3},{%4,%5,%6,%7},{%8,%9},{%0,%1,%2,%3};"
        : "+f"(d[0]), "+f"(d[1]), "+f"(d[2]), "+f"(d[3])
        : "r"(a0), "r"(a1), "r"(a2), "r"(a3), "r"(b0), "r"(b1));
}

__device__ __forceinline__ void cp_copy16(void* dst, const void* src, int n16, int tid){
    uint32_t sbase = (uint32_t)__cvta_generic_to_shared(dst);
    const uint4* s = (const uint4*)src;
    for (int i = tid; i < n16; i += NTHR)
        asm volatile("cp.async.cg.shared.global [%0], [%1], 16;"
                     :: "r"(sbase + i*16), "l"(s + i));
}
#define CP_COMMIT() asm volatile("cp.async.commit_group;" ::: "memory")
#define CP_WAIT0()  asm volatile("cp.async.wait_group 0;" ::: "memory")
#define PAIR_BAR(id) asm volatile("bar.sync %0, 64;" :: "r"(id) : "memory")

// ---------------- one-shot weight packing (uint4 n-pair fragments) --------
// W1: entry[rs][rowq=kt*4+tig][p*8+g] =
//   { h2(w[2kp],w[2kp+1]) @n1, h2(w[2kp+8],w[2kp+9]) @n1, same @n2 },
//   kp = kt*8+tig, n1 = 16p+g, n2 = 16p+8+g.
__global__ void pack_weights(const float* __restrict__ rw1,
                             const float* __restrict__ rw2)
{
    int i = blockIdx.x * blockDim.x + threadIdx.x;
    if (i < NRULES*3*16*64){
        int e    = i & 63;
        int rowq = (i >> 6) & 15;
        int rs   = i >> 10;
        int p = e >> 3, g = e & 7;
        int kt = rowq >> 2, tig = rowq & 3;
        int kp = kt*8 + tig;
        int n1 = 16*p + g, n2 = n1 + 8;
        const float* w = rw1 + ((size_t)(rs/3)*K1 + (rs%3)*64) * HID;
        float2 a1, a2, b1, b2;
        a1.x = w[(size_t)(2*kp)   * HID + n1];
        a1.y = w[(size_t)(2*kp+1) * HID + n1];
        a2.x = w[(size_t)(2*kp+8) * HID + n1];
        a2.y = w[(size_t)(2*kp+9) * HID + n1];
        b1.x = w[(size_t)(2*kp)   * HID + n2];
        b1.y = w[(size_t)(2*kp+1) * HID + n2];
        b2.x = w[(size_t)(2*kp+8) * HID + n2];
        b2.y = w[(size_t)(2*kp+9) * HID + n2];
        g_w1p[(size_t)rs*16*W1P4 + rowq*W1P4 + e] =
            make_uint4(pack_f16(a1), pack_f16(a2), pack_f16(b1), pack_f16(b2));
    } else {
        int q = i - NRULES*3*16*64;
        if (q >= NRULES*32*32) return;
        int e    = q & 31;
        int rowq = (q >> 5) & 31;
        int r    = q >> 10;
        int p = e >> 3, g = e & 7;
        int ktg = rowq >> 2, tig = rowq & 3;
        int kp = ktg*8 + tig;
        int n1 = 16*p + g, n2 = n1 + 8;
        const float* w = rw2 + (size_t)r * HID * D_MODEL;
        float2 a1, a2, b1, b2;
        a1.x = w[(size_t)(2*kp)   * D_MODEL + n1];
        a1.y = w[(size_t)(2*kp+1) * D_MODEL + n1];
        a2.x = w[(size_t)(2*kp+8) * D_MODEL + n1];
        a2.y = w[(size_t)(2*kp+9) * D_MODEL + n1];
        b1.x = w[(size_t)(2*kp)   * D_MODEL + n2];
        b1.y = w[(size_t)(2*kp+1) * D_MODEL + n2];
        b2.x = w[(size_t)(2*kp+8) * D_MODEL + n2];
        b2.y = w[(size_t)(2*kp+9) * D_MODEL + n2];
        g_w2p[(size_t)r*32*W2P4 + rowq*W2P4 + e] =
            make_uint4(pack_f16(a1), pack_f16(a2), pack_f16(b1), pack_f16(b2));
    }
}

// ---------------- control kernel ----------------
__global__ void control_kernel(
    const float* __restrict__ c,
    const float* __restrict__ sw1, const float* __restrict__ sb1,
    const float* __restrict__ sw2, const float* __restrict__ sb2,
    const float* __restrict__ tw1, const float* __restrict__ tb1,
    const float* __restrict__ tw2, const float* __restrict__ tb2,
    const float* __restrict__ qw1, const float* __restrict__ qb1,
    const float* __restrict__ qw2, const float* __restrict__ qb2)
{
    __shared__ float cs[128], h1[64], h2[32], h3[32];
    int t = threadIdx.x;
    if (t < 128) cs[t] = c[t];
    __syncthreads();
    if (t < 64){
        float a = sb1[t];
        for (int k = 0; k < 128; k++) a += cs[k] * sw1[k*64 + t];
        h1[t] = gelu_exact(a);
    } else if (t < 96){
        int i = t - 64; float a = tb1[i];
        for (int k = 0; k < 128; k++) a += cs[k] * tw1[k*32 + i];
        h2[i] = gelu_exact(a);
    } else {
        int i = t - 96; float a = qb1[i];
        for (int k = 0; k < 128; k++) a += cs[k] * qw1[k*32 + i];
        h3[i] = gelu_exact(a);
    }
    __syncthreads();
    if (t == 0){
        float l[4], mx = -1e30f;
        for (int r = 0; r < 4; r++){
            float a = sb2[r];
            for (int i = 0; i < 64; i++) a += h1[i] * sw2[i*4 + r];
            l[r] = a; mx = fmaxf(mx, a);
        }
        float s = 0.f;
        for (int r = 0; r < 4; r++){ l[r] = expf(l[r]-mx); s += l[r]; }
        for (int r = 0; r < 4; r++) g_rw[r] = l[r]/s;
    }
    if (t == 1){
        float l[7], mx = -1e30f;
        for (int q = 0; q < 7; q++){
            float a = tb2[q];
            for (int i = 0; i < 32; i++) a += h2[i] * tw2[i*7 + q];
            l[q] = a; mx = fmaxf(mx, a);
        }
        float s = 0.f;
        for (int q = 0; q < 7; q++){ l[q] = expf(l[q]-mx); s += l[q]; }
        float nf = 0.f;
        for (int q = 0; q < 7; q++) nf += (l[q]/s) * (float)(q+2);
        int n = (int)(nf + 0.5f);
        g_nev = n < 2 ? 2 : (n > 8 ? 8 : n);
    }
    if (t == 2){
        float v = qb2[0];
        for (int i = 0; i < 32; i++) v += h3[i] * qw2[i];
        g_alpha = 0.1f + 0.8f / (1.0f + expf(-v));
    }
}

// one GEMM1 segment: 4 k-tiles x 4 n-pairs x 1 term
__device__ __forceinline__ void gemm1_seg(float acc[8][4], const uint4* wseg,
    const uint2* aprf, const uint2* bprf, int half, int g, int tig)
{
    #pragma unroll
    for (int kt = 0; kt < 4; kt++){
        uint2 Aa = aprf[kt*4 + tig];   // row g:   {h2(kp), h2(kp+4)}
        uint2 Ab = bprf[kt*4 + tig];   // row g+8
        const uint4* br = wseg + (size_t)(kt*4 + tig)*W1P4;
        #pragma unroll
        for (int p = 0; p < 4; p++){
            uint4 qv = br[(half*4 + p)*8 + g];
            mma_f16(acc[2*p],   Aa.x, Ab.x, Aa.y, Ab.y, qv.x, qv.y);
            mma_f16(acc[2*p+1], Aa.x, Ab.x, Aa.y, Ab.y, qv.z, qv.w);
        }
    }
}

// ---------------- evolve step (64 tokens/CTA, 2 CTAs/SM, pure fp16) -------
__global__ void __launch_bounds__(NTHR, 2)
step_kernel(const float* __restrict__ cells_in,
            const float* __restrict__ rb1, const float* __restrict__ rb2,
            int j)
{
    if (j >= g_nev) return;

    extern __shared__ char smc[];
    uint2*  cpf = (uint2*)smc;
    uint4*  r0  = (uint4*)(smc + OFF_R0B);
    uint4*  r1  = (uint4*)(smc + OFF_R1B);
    float4* xb  = (float4*)(smc + OFF_XCHB);

    const float* src = (j == 0) ? cells_in : ((j & 1) ? g_buf0 : g_buf1);
    float*       dst = (j & 1) ? g_buf1 : g_buf0;

    const int tid  = threadIdx.x;
    const int w    = tid >> 5;
    const int lane = tid & 31;
    const int g    = lane >> 2;
    const int tig  = lane & 3;
    const int half = w & 1;           // n-half within pair
    const int wp   = w >> 1;          // pair id 0..3
    const int m0   = wp * 16;

    const int brow = blockIdx.x >> 7;
    const int t0   = (blockIdx.x & 127) << 6;
    const float* rowbase = src + (size_t)brow * TT * D_MODEL;

    // prefetch rule0 seg0 -> R0 while building the cells fragment tile
    cp_copy16(r0, g_w1p, SEG_U4, tid);
    CP_COMMIT();

    // cells halo in fragment layout: rows t0-1..t0+64 (66), 16 entries/row
    // entry e = kt*4+tig2: {h2(x[16kt+2tig2], x[+1]), h2(x[+8], x[+9])}
    for (int i = tid; i < 66*16; i += NTHR){
        int row = i >> 4, e = i & 15;
        int t = (t0 - 1 + row) & (TT - 1);
        int c0 = 16*(e >> 2) + 2*(e & 3);
        const float* rp = rowbase + (size_t)t * D_MODEL;
        float2 v0 = *(const float2*)(rp + c0);
        float2 v1 = *(const float2*)(rp + c0 + 8);
        cpf[row*CPF + e] = make_uint2(pack_f16(v0), pack_f16(v1));
    }
    CP_WAIT0();
    __syncthreads();

    float outa[16];
    #pragma unroll
    for (int i = 0; i < 16; i++) outa[i] = 0.0f;

    for (int r = 0; r < NRULES; r++){
        const uint2* aprf0 = cpf + (size_t)(m0 + 1 + g) * CPF;   // cells[t]
        const uint2* aprf1 = cpf + (size_t)(m0 + 0 + g) * CPF;   // cells[t-1]
        const uint2* aprf2 = cpf + (size_t)(m0 + 2 + g) * CPF;   // cells[t+1]

        float acc[8][4];
        #pragma unroll
        for (int a = 0; a < 8; a++){
            acc[a][0]=0.f; acc[a][1]=0.f; acc[a][2]=0.f; acc[a][3]=0.f;
        }

        // seg0 in R0. prefetch seg1 -> R1; compute seg0
        cp_copy16(r1, g_w1p + (size_t)(r*3+1)*16*W1P4, SEG_U4, tid);
        CP_COMMIT();
        gemm1_seg(acc, r0, aprf0, aprf0 + 8*CPF, half, g, tig);
        CP_WAIT0();
        __syncthreads();

        // prefetch seg2 -> R0; compute seg1
        cp_copy16(r0, g_w1p + (size_t)(r*3+2)*16*W1P4, SEG_U4, tid);
        CP_COMMIT();
        gemm1_seg(acc, r1, aprf1, aprf1 + 8*CPF, half, g, tig);
        CP_WAIT0();
        __syncthreads();

        // prefetch W2 -> R1; compute seg2
        cp_copy16(r1, g_w2p + (size_t)r*32*W2P4, W2_U4, tid);
        CP_COMMIT();
        gemm1_seg(acc, r0, aprf2, aprf2 + 8*CPF, half, g, tig);
        CP_WAIT0();
        __syncthreads();

        // prefetch next rule seg0 -> R0 (overlaps epi+GEMM2)
        if (r < NRULES-1){
            cp_copy16(r0, g_w1p + (size_t)((r+1)*3)*16*W1P4, SEG_U4, tid);
            CP_COMMIT();
        }

        // epi1 in registers: h = gelu(C1+b1) -> GEMM2 A fragments (fp16)
        uint32_t fh[4][4];
        #pragma unroll
        for (int ktl = 0; ktl < 4; ktl++){
            #pragma unroll
            for (int sub = 0; sub < 2; sub++){
                int ntl = 2*ktl + sub;
                int c   = (half*8 + ntl)*8 + 2*tig;
                const float2 bb = __ldg((const float2*)(rb1 + r*HID + c));
                float2 va, vb;
                va.x = gelu_fast(acc[ntl][0] + bb.x);
                va.y = gelu_fast(acc[ntl][1] + bb.y);
                vb.x = gelu_fast(acc[ntl][2] + bb.x);
                vb.y = gelu_fast(acc[ntl][3] + bb.y);
                fh[ktl][sub*2]   = pack_f16(va);
                fh[ktl][sub*2+1] = pack_f16(vb);
            }
        }

        // GEMM2: k-chunks half*4..+3, 4 n-pairs, 1 term (W2 in R1)
        float acc2[8][4];
        #pragma unroll
        for (int a = 0; a < 8; a++){
            acc2[a][0]=0.f; acc2[a][1]=0.f; acc2[a][2]=0.f; acc2[a][3]=0.f;
        }
        #pragma unroll
        for (int ktl = 0; ktl < 4; ktl++){
            const uint4* br = r1 + (size_t)((half*4+ktl)*4 + tig)*W2P4;
            #pragma unroll
            for (int p = 0; p < 4; p++){
                uint4 qv = br[p*8 + g];
                mma_f16(acc2[2*p],   fh[ktl][0],fh[ktl][1],fh[ktl][2],fh[ktl][3], qv.x, qv.y);
                mma_f16(acc2[2*p+1], fh[ktl][0],fh[ktl][1],fh[ktl][2],fh[ktl][3], qv.z, qv.w);
            }
        }

        // exchange partner's tiles via dedicated xchg buffer + pair barrier
        {
            const int sbase = (wp*2 + half)*4;
            const int pnt   = (1 - half)*4;
            #pragma unroll
            for (int q = 0; q < 4; q++)
                xb[(sbase + q)*32 + lane] = make_float4(
                    acc2[pnt+q][0], acc2[pnt+q][1], acc2[pnt+q][2], acc2[pnt+q][3]);
        }
        PAIR_BAR(1 + wp);

        // finalize: own partial + partner partial -> tanh -> outa
        {
            const int pbase = (wp*2 + (1 - half))*4;
            const int ont   = half*4;
            const float rr = g_rw[r];
            #pragma unroll
            for (int q = 0; q < 4; q++){
                float4 pp = xb[(pbase + q)*32 + lane];
                int c = (ont + q)*8 + 2*tig;
                const float2 bb = __ldg((const float2*)(rb2 + r*D_MODEL + c));
                outa[q*4+0] += rr * tanh_fast(acc2[ont+q][0] + pp.x + bb.x);
                outa[q*4+1] += rr * tanh_fast(acc2[ont+q][1] + pp.y + bb.y);
                outa[q*4+2] += rr * tanh_fast(acc2[ont+q][2] + pp.z + bb.x);
                outa[q*4+3] += rr * tanh_fast(acc2[ont+q][3] + pp.w + bb.y);
            }
        }
        PAIR_BAR(1 + wp);      // xchg slot reusable next rule
        CP_WAIT0();
        __syncthreads();       // next seg0 staged; R1 free
    }

    // residual mix + store
    {
        const float al = g_alpha, om = 1.0f - al;
        const float* sra = src + ((size_t)brow*TT + t0 + m0 + g) * D_MODEL;
        const float* srb = src + ((size_t)brow*TT + t0 + m0 + g + 8) * D_MODEL;
        float* da = dst + ((size_t)brow*TT + t0 + m0 + g) * D_MODEL;
        float* db = dst + ((size_t)brow*TT + t0 + m0 + g + 8) * D_MODEL;
        #pragma unroll
        for (int q = 0; q < 4; q++){
            int c = (half*4 + q)*8 + 2*tig;
            float2 cva = __ldg((const float2*)(sra + c));
            float2 cvb = __ldg((const float2*)(srb + c));
            float2 oa, ob;
            oa.x = al*cva.x + om*outa[q*4+0];
            oa.y = al*cva.y + om*outa[q*4+1];
            ob.x = al*cvb.x + om*outa[q*4+2];
            ob.y = al*cvb.y + om*outa[q*4+3];
            *(float2*)(da + c) = oa;
            *(float2*)(db + c) = ob;
        }
    }
}

// ---------------- final LayerNorm ----------------
__global__ void __launch_bounds__(256)
ln_kernel(const float* __restrict__ g, const float* __restrict__ b,
          float* __restrict__ out)
{
    const float* src = ((g_nev - 1) & 1) ? g_buf1 : g_buf0;
    int tok  = blockIdx.x * 8 + (threadIdx.x >> 5);
    int lane = threadIdx.x & 31;
    float2 v = ((const float2*)(src + (size_t)tok * D_MODEL))[lane];
    float s = v.x + v.y;
    #pragma unroll
    for (int o = 16; o; o >>= 1) s += __shfl_xor_sync(0xffffffffu, s, o);
    float mu = s * (1.0f/64.0f);
    float dx = v.x - mu, dy = v.y - mu;
    float ss = dx*dx + dy*dy;
    #pragma unroll
    for (int o = 16; o; o >>= 1) ss += __shfl_xor_sync(0xffffffffu, ss, o);
    float rstd = rsqrtf(ss * (1.0f/64.0f) + LN_EPS);
    float2 gg = ((const float2*)g)[lane];
    float2 bb = ((const float2*)b)[lane];
    float2 ov;
    ov.x = dx * rstd * gg.x + bb.x;
    ov.y = dy * rstd * gg.y + bb.y;
    ((float2*)(out + (size_t)tok * D_MODEL))[lane] = ov;
}

// ---------------- launch ----------------
extern "C" void kernel_launch(void* const* d_in, const int* in_sizes, int n_in,
                              void* d_out, int out_size)
{
    const float* cells = (const float*)d_in[0];
    cudaFuncSetAttribute(step_kernel,
                         cudaFuncAttributeMaxDynamicSharedMemorySize, SMEM_BYTES);

    control_kernel<<<1, 128>>>((const float*)d_in[1],
        (const float*)d_in[6],  (const float*)d_in[7],
        (const float*)d_in[8],  (const float*)d_in[9],
        (const float*)d_in[10], (const float*)d_in[11],
        (const float*)d_in[12], (const float*)d_in[13],
        (const float*)d_in[14], (const float*)d_in[15],
        (const float*)d_in[16], (const float*)d_in[17]);

    pack_weights<<<(NRULES*3*16*64 + NRULES*32*32 + 255)/256, 256>>>(
        (const float*)d_in[2], (const float*)d_in[4]);

    for (int j = 0; j < 8; j++)
        step_kernel<<<NBLK, NTHR, SMEM_BYTES>>>(cells,
            (const float*)d_in[3], (const float*)d_in[5], j);

    ln_kernel<<<NTOK/8, 256>>>((const float*)d_in[18], (const float*)d_in[19],
                               (float*)d_out);
}